// round 16
// baseline (speedup 1.0000x reference)
#include <cuda_runtime.h>
#include <cuda_bf16.h>
#include <cstdint>

// Single fused launch, grid=512 x 256 threads, 2 tiles of 256 positions per block.
// Block-cooperative cp.async (LDGSTS) double-buffered z tiles:
//   issue A -> stage weights -> build coefficients -> issue B -> compute A -> compute B
// Compute: single pass over s with 4-head accumulation, z read from shared.
// NOTE: needs >48KB smem -> cudaFuncSetAttribute opt-in in kernel_launch
// (immediate API, graph-capture-safe; not a sync/alloc/memcpy).
//
// Coefficients C[104], per head h (base h*25):
//   [0..8]  P[i][j] (scaled log2e/sqrt(8)), [9..11] p[i],
//   [16..24] G[c][i], [100..102] g0[c].  Score offset cancels in softmax.

__device__ __forceinline__ float fast_ex2(float x) {
    float r; asm("ex2.approx.f32 %0, %1;" : "=f"(r) : "f"(x)); return r;
}
__device__ __forceinline__ float fast_rcp(float x) {
    float r; asm("rcp.approx.f32 %0, %1;" : "=f"(r) : "f"(x)); return r;
}
__device__ __forceinline__ void cp_async16(uint32_t saddr, const float* gaddr) {
    asm volatile("cp.async.cg.shared.global [%0], [%1], 16;" :: "r"(saddr), "l"(gaddr));
}
__device__ __forceinline__ void cp_commit() {
    asm volatile("cp.async.commit_group;" ::: "memory");
}
template <int N> __device__ __forceinline__ void cp_wait() {
    asm volatile("cp.async.wait_group %0;" :: "n"(N) : "memory");
}

static constexpr int TILE_F = 24 * 256;   // floats per tile (24 rows x 256 pos)

__device__ __forceinline__ void load_tile_async(const float* __restrict__ z,
                                                float* __restrict__ buf,
                                                int tile, int t)
{
    const int pos0 = tile << 8;                 // tile * 256
    const int b    = pos0 >> 16;
    const int hw   = pos0 & 65535;
    const float* g = z + (size_t)b * 1572864 + hw;
    const uint32_t s0 = (uint32_t)__cvta_generic_to_shared(buf);
#pragma unroll
    for (int k = 0; k < 6; k++) {
        const int idx = t + (k << 8);           // 0..1535 (float4 index)
        const int row = idx >> 6;               // 0..23  = s*3+c
        const int col = idx & 63;               // float4 within row
        cp_async16(s0 + (uint32_t)(row * 256 + col * 4) * 4u,
                   g + (size_t)row * 65536 + col * 4);
    }
}

__device__ __forceinline__ void compute_tile(const float* __restrict__ buf,
                                             const float* __restrict__ C,
                                             float* __restrict__ out,
                                             int tile, int t)
{
    const int pos0 = tile << 8;
    const int b    = pos0 >> 16;
    const int hw   = (pos0 & 65535) + t;

    // z_last (s=7): rows 21,22,23
    const float zl0 = buf[21 * 256 + t];
    const float zl1 = buf[22 * 256 + t];
    const float zl2 = buf[23 * 256 + t];

    // u[h][i] = P[h]·z_last + p[h]  (12 values, scaled log2e/sqrt(8))
    float u[12];
#pragma unroll
    for (int h = 0; h < 4; h++) {
        const float* Ph = &C[h * 25];
        u[h * 3 + 0] = Ph[0] * zl0 + Ph[1] * zl1 + Ph[2] * zl2 + Ph[9];
        u[h * 3 + 1] = Ph[3] * zl0 + Ph[4] * zl1 + Ph[5] * zl2 + Ph[10];
        u[h * 3 + 2] = Ph[6] * zl0 + Ph[7] * zl1 + Ph[8] * zl2 + Ph[11];
    }

    float sum[4] = {0.f, 0.f, 0.f, 0.f};
    float zb[12];
#pragma unroll
    for (int i = 0; i < 12; i++) zb[i] = 0.f;

#pragma unroll
    for (int s = 0; s < 8; s++) {
        const float z0 = buf[(s * 3 + 0) * 256 + t];
        const float z1 = buf[(s * 3 + 1) * 256 + t];
        const float z2 = buf[(s * 3 + 2) * 256 + t];
#pragma unroll
        for (int h = 0; h < 4; h++) {
            const float sc = u[h * 3] * z0 + u[h * 3 + 1] * z1 + u[h * 3 + 2] * z2;
            const float e  = fast_ex2(sc);      // scores O(1): no max-subtract
            sum[h] += e;
            zb[h * 3 + 0] += e * z0;
            zb[h * 3 + 1] += e * z1;
            zb[h * 3 + 2] += e * z2;
        }
    }

    float o0 = C[100], o1 = C[101], o2 = C[102];
#pragma unroll
    for (int h = 0; h < 4; h++) {
        const float* Ph = &C[h * 25];
        const float inv = fast_rcp(sum[h]);
        const float b0 = zb[h * 3 + 0] * inv;
        const float b1 = zb[h * 3 + 1] * inv;
        const float b2 = zb[h * 3 + 2] * inv;
        o0 += Ph[16] * b0 + Ph[17] * b1 + Ph[18] * b2;
        o1 += Ph[19] * b0 + Ph[20] * b1 + Ph[21] * b2;
        o2 += Ph[22] * b0 + Ph[23] * b1 + Ph[24] * b2;
    }

    float* op = out + (size_t)b * 196608 + hw;
    op[0]      = o0;
    op[65536]  = o1;
    op[131072] = o2;
}

__global__ void __launch_bounds__(256, 4) attn_fused_kernel(
    const float* __restrict__ z,
    const float* __restrict__ W_in, const float* __restrict__ b_in,
    const float* __restrict__ W_q,  const float* __restrict__ b_q,
    const float* __restrict__ W_k,  const float* __restrict__ b_k,
    const float* __restrict__ W_v,  const float* __restrict__ b_v,
    const float* __restrict__ W_o,  const float* __restrict__ b_o,
    float* __restrict__ out)
{
    extern __shared__ float pool[];             // 2 * TILE_F floats = 48KB dynamic
    __shared__ float C[104];                    // static, on top (needs opt-in)

    float* bufA = pool;
    float* bufB = pool + TILE_F;
    // Prologue scratch aliases bufB (B's cp.async issues only after phase 2).
    float* sWT  = pool + TILE_F;                // 3*1056 = 3168
    float* sIn  = pool + TILE_F + 3168;         // 128
    float* sAq  = pool + TILE_F + 3296;         // 96  [o*3+i]
    float* sAk  = pool + TILE_F + 3392;         // 96
    float* sAv  = pool + TILE_F + 3488;         // 96
    float* sCg  = pool + TILE_F + 3584;         // 96  [m*32+o]

    const int t = threadIdx.x;
    const int tg0 = blockIdx.x << 1;            // first of 2 tiles

    // ---- Issue tile A loads immediately (latency hides behind prologue) ----
    load_tile_async(z, bufA, tg0, t);
    cp_commit();

    // ---- Phase 0: stage weights (coalesced LDG -> transposed padded STS) ----
#pragma unroll
    for (int m = 0; m < 3; m++) {
        const float* Wm = (m == 0) ? W_q : (m == 1) ? W_k : W_v;
#pragma unroll
        for (int k = 0; k < 4; k++) {
            const int idx = t + (k << 8);       // 0..1023
            const int o = idx >> 5, j = idx & 31;
            sWT[m * 1056 + j * 33 + o] = Wm[idx];
        }
    }
    if (t < 96)       sIn[t] = W_in[t];
    else if (t < 128) sIn[t] = b_in[t - 96];
    __syncthreads();

    // ---- Phase 1: A_m[o][i] = W_m[o,:]·W_in[:,i];  c_m[o] = b_m[o]+W_m[o,:]·b_in ----
    if (t < 96) {
        const int m = t >> 5, o = t & 31;
        const float* wt = &sWT[m * 1056 + o];
        float a0 = 0.f, a1 = 0.f, a2 = 0.f, ac = 0.f;
#pragma unroll 8
        for (int j = 0; j < 32; j++) {
            const float w = wt[j * 33];
            a0 += w * sIn[j * 3 + 0];
            a1 += w * sIn[j * 3 + 1];
            a2 += w * sIn[j * 3 + 2];
            ac += w * sIn[96 + j];
        }
        const float* bm = (m == 0) ? b_q : (m == 1) ? b_k : b_v;
        ac += bm[o];
        float* A = (m == 0) ? sAq : (m == 1) ? sAk : sAv;
        A[o * 3 + 0] = a0; A[o * 3 + 1] = a1; A[o * 3 + 2] = a2;
        sCg[m * 32 + o] = ac;
    }
    __syncthreads();

    // ---- Phase 2: per-head bilinear composites into C[] ----
    const float scale2 = 0.35355339059327373f * 1.4426950408889634f;  // log2e/sqrt(8)
    if (t < 103) {
        const int idx = t;
        if (idx < 100) {
            const int h = idx / 25, e = idx - h * 25;
            const int base = h * 8;
            float val = 0.f;
            if (e < 9) {
                const int i = e / 3, j = e - i * 3;
#pragma unroll
                for (int d = 0; d < 8; d++)
                    val += sAk[(base + d) * 3 + i] * sAq[(base + d) * 3 + j];
                val *= scale2;
            } else if (e < 12) {
                const int i = e - 9;
#pragma unroll
                for (int d = 0; d < 8; d++)
                    val += sAk[(base + d) * 3 + i] * sCg[base + d];   // cq
                val *= scale2;
            } else if (e < 16) {
                val = 0.f;                      // score offset cancels in softmax
            } else {
                const int e2 = e - 16;
                const int c = e2 / 3, i = e2 - c * 3;
#pragma unroll
                for (int d = 0; d < 8; d++)
                    val += W_o[c * 32 + base + d] * sAv[(base + d) * 3 + i];
            }
            C[h * 25 + e] = val;
        } else {
            const int c = idx - 100;
            float val = b_o[c];
#pragma unroll 8
            for (int d = 0; d < 32; d++) val += W_o[c * 32 + d] * sCg[64 + d];  // cv
            C[100 + c] = val;
        }
    }
    __syncthreads();   // prologue done; bufB region free

    // ---- Issue tile B loads (hide behind tile A compute) ----
    load_tile_async(z, bufB, tg0 + 1, t);
    cp_commit();

    // ---- Tile A: wait (group A older; <=1 pending keeps B in flight) ----
    cp_wait<1>();
    __syncthreads();
    compute_tile(bufA, C, out, tg0, t);

    // ---- Tile B ----
    cp_wait<0>();
    __syncthreads();
    compute_tile(bufB, C, out, tg0 + 1, t);
}

extern "C" void kernel_launch(void* const* d_in, const int* in_sizes, int n_in,
                              void* d_out, int out_size)
{
    const float* z    = (const float*)d_in[0];
    const float* W_in = (const float*)d_in[1];
    const float* b_in = (const float*)d_in[2];
    const float* W_q  = (const float*)d_in[3];
    const float* b_q  = (const float*)d_in[4];
    const float* W_k  = (const float*)d_in[5];
    const float* b_k  = (const float*)d_in[6];
    const float* W_v  = (const float*)d_in[7];
    const float* b_v  = (const float*)d_in[8];
    const float* W_o  = (const float*)d_in[9];
    const float* b_o  = (const float*)d_in[10];
    float* out = (float*)d_out;

    // Opt in to >48KB smem (dynamic 48KB + static C). Immediate API call,
    // no stream interaction -> graph-capture-safe; idempotent per call.
    cudaFuncSetAttribute(attn_fused_kernel,
                         cudaFuncAttributeMaxDynamicSharedMemorySize, 65536);

    // 512 blocks x 2 tiles x 256 positions = 262144; single wave at 4 CTA/SM.
    const int smem = 2 * TILE_F * sizeof(float);   // 49152 B dynamic
    attn_fused_kernel<<<512, 256, smem>>>(z, W_in, b_in, W_q, b_q, W_k, b_k,
                                          W_v, b_v, W_o, b_o, out);
}

// round 17
// speedup vs baseline: 1.4320x; 1.4320x over previous
#include <cuda_runtime.h>
#include <cuda_bf16.h>
#include <cstdint>

// Single fused launch, grid=1024 x 256, ONE position per thread (proven shape:
// direct LDG -> registers). Coefficients are packed as float4 so the per-thread
// coefficient traffic is ~25 LDS.128 instead of ~100 LDS.32.
//
// Packed layout sC4[33] (float4):
//   per head h, base h*8:
//     [0..2] {P[i][0],P[i][1],P[i][2], p[i]}  (score coeffs, scaled log2e/sqrt(8))
//     [3..5] {G[c][0],G[c][1],G[c][2], -   }  (output coeffs)
//   [32]     {g0[0],g0[1],g0[2], -}           (constant output term)
// Score offset cancels in softmax (shift invariance) and is dropped.

__device__ __forceinline__ float fast_ex2(float x) {
    float r; asm("ex2.approx.f32 %0, %1;" : "=f"(r) : "f"(x)); return r;
}
__device__ __forceinline__ float fast_rcp(float x) {
    float r; asm("rcp.approx.f32 %0, %1;" : "=f"(r) : "f"(x)); return r;
}

__global__ void __launch_bounds__(256, 4) attn_fused_kernel(
    const float* __restrict__ z,
    const float* __restrict__ W_in, const float* __restrict__ b_in,
    const float* __restrict__ W_q,  const float* __restrict__ b_q,
    const float* __restrict__ W_k,  const float* __restrict__ b_k,
    const float* __restrict__ W_v,  const float* __restrict__ b_v,
    const float* __restrict__ W_o,  const float* __restrict__ b_o,
    float* __restrict__ out, int n_pos)
{
    __shared__ float sWT[3 * 1056];            // W_m transposed: [m][j*33 + o]
    __shared__ float sIn[128];                 // W_in (96) + b_in (32)
    __shared__ float sAq[96], sAk[96], sAv[96];// [o*3+i]
    __shared__ float sCg[96];                  // cq,ck,cv  [m*32+o]
    __shared__ float4 sC4[33];                 // packed coefficients

    const int t = threadIdx.x;

    // ---- Phase 0: coalesced staging of weights ----
#pragma unroll
    for (int m = 0; m < 3; m++) {
        const float* Wm = (m == 0) ? W_q : (m == 1) ? W_k : W_v;
#pragma unroll
        for (int k = 0; k < 4; k++) {
            const int idx = t + (k << 8);       // 0..1023
            const int o = idx >> 5, j = idx & 31;
            sWT[m * 1056 + j * 33 + o] = Wm[idx];
        }
    }
    if (t < 96)       sIn[t] = W_in[t];
    else if (t < 128) sIn[t] = b_in[t - 96];
    __syncthreads();

    // ---- Phase 1: A_m[o][i] = W_m[o,:]·W_in[:,i];  c_m[o] = b_m[o]+W_m[o,:]·b_in ----
    if (t < 96) {
        const int m = t >> 5, o = t & 31;
        const float* wt = &sWT[m * 1056 + o];
        float a0 = 0.f, a1 = 0.f, a2 = 0.f, ac = 0.f;
#pragma unroll 8
        for (int j = 0; j < 32; j++) {
            const float w = wt[j * 33];
            a0 += w * sIn[j * 3 + 0];
            a1 += w * sIn[j * 3 + 1];
            a2 += w * sIn[j * 3 + 2];
            ac += w * sIn[96 + j];
        }
        const float* bm = (m == 0) ? b_q : (m == 1) ? b_k : b_v;
        ac += bm[o];
        float* A = (m == 0) ? sAq : (m == 1) ? sAk : sAv;
        A[o * 3 + 0] = a0; A[o * 3 + 1] = a1; A[o * 3 + 2] = a2;
        sCg[m * 32 + o] = ac;
    }
    __syncthreads();

    // ---- Phase 2: per-head bilinear composites into packed sC4 ----
    const float scale2 = 0.35355339059327373f * 1.4426950408889634f;  // log2e/sqrt(8)
    float* Cw = (float*)sC4;
    if (t < 103) {
        const int idx = t;
        if (idx < 100) {
            const int h = idx / 25, e = idx - h * 25;
            const int base = h * 8;
            if (e < 9) {                        // P[i][j]
                const int i = e / 3, j = e - i * 3;
                float val = 0.f;
#pragma unroll
                for (int d = 0; d < 8; d++)
                    val += sAk[(base + d) * 3 + i] * sAq[(base + d) * 3 + j];
                Cw[(h * 8 + i) * 4 + j] = val * scale2;
            } else if (e < 12) {                // p[i]
                const int i = e - 9;
                float val = 0.f;
#pragma unroll
                for (int d = 0; d < 8; d++)
                    val += sAk[(base + d) * 3 + i] * sCg[base + d];   // cq
                Cw[(h * 8 + i) * 4 + 3] = val * scale2;
            } else if (e >= 16) {               // G[c][i]
                const int e2 = e - 16;
                const int c = e2 / 3, i = e2 - c * 3;
                float val = 0.f;
#pragma unroll
                for (int d = 0; d < 8; d++)
                    val += W_o[c * 32 + base + d] * sAv[(base + d) * 3 + i];
                Cw[(h * 8 + 3 + c) * 4 + i] = val;
            }
            // e in 12..15: score offset — cancels in softmax, not stored.
        } else {                                // g0[c]
            const int c = idx - 100;
            float val = b_o[c];
#pragma unroll 8
            for (int d = 0; d < 32; d++) val += W_o[c * 32 + d] * sCg[64 + d];  // cv
            Cw[32 * 4 + c] = val;
        }
    }
    __syncthreads();

    // ---- Phase 3: one position per thread, direct LDG -> regs ----
    const int p = blockIdx.x * blockDim.x + threadIdx.x;
    if (p >= n_pos) return;

    const int b  = p >> 16;          // p / 65536
    const int hw = p & 65535;

    // z layout (B, T=8, C=3, 65536): elem (b,s,c,hw) at ((b*8+s)*3+c)*65536 + hw
    float zz[8][3];
    const float* zp = z + (size_t)b * 1572864 + hw;
#pragma unroll
    for (int s = 0; s < 8; s++)
#pragma unroll
        for (int c = 0; c < 3; c++)
            zz[s][c] = zp[(size_t)(s * 3 + c) * 65536];

    const float zl0 = zz[7][0], zl1 = zz[7][1], zl2 = zz[7][2];

    const float4 gg = sC4[32];
    float o0 = gg.x, o1 = gg.y, o2 = gg.z;

#pragma unroll
    for (int h = 0; h < 4; h++) {
        // u_i = P[i]·z_last + p[i]  — 3 x LDS.128
        const float4 r0 = sC4[h * 8 + 0];
        const float4 r1 = sC4[h * 8 + 1];
        const float4 r2 = sC4[h * 8 + 2];
        const float u0 = r0.x * zl0 + r0.y * zl1 + r0.z * zl2 + r0.w;
        const float u1 = r1.x * zl0 + r1.y * zl1 + r1.z * zl2 + r1.w;
        const float u2 = r2.x * zl0 + r2.y * zl1 + r2.z * zl2 + r2.w;

        float sum = 0.f, zb0 = 0.f, zb1 = 0.f, zb2 = 0.f;
#pragma unroll
        for (int s = 0; s < 8; s++) {
            const float sc = u0 * zz[s][0] + u1 * zz[s][1] + u2 * zz[s][2];
            const float e  = fast_ex2(sc);      // scores O(1): no max-subtract
            sum += e;
            zb0 += e * zz[s][0];
            zb1 += e * zz[s][1];
            zb2 += e * zz[s][2];
        }
        const float inv = fast_rcp(sum);
        zb0 *= inv; zb1 *= inv; zb2 *= inv;

        // out += G·zbar  — 3 x LDS.128
        const float4 g0r = sC4[h * 8 + 3];
        const float4 g1r = sC4[h * 8 + 4];
        const float4 g2r = sC4[h * 8 + 5];
        o0 += g0r.x * zb0 + g0r.y * zb1 + g0r.z * zb2;
        o1 += g1r.x * zb0 + g1r.y * zb1 + g1r.z * zb2;
        o2 += g2r.x * zb0 + g2r.y * zb1 + g2r.z * zb2;
    }

    // out layout (B, 3, 65536)
    float* op = out + (size_t)b * 196608 + hw;
    op[0]      = o0;
    op[65536]  = o1;
    op[131072] = o2;
}

extern "C" void kernel_launch(void* const* d_in, const int* in_sizes, int n_in,
                              void* d_out, int out_size)
{
    const float* z    = (const float*)d_in[0];
    const float* W_in = (const float*)d_in[1];
    const float* b_in = (const float*)d_in[2];
    const float* W_q  = (const float*)d_in[3];
    const float* b_q  = (const float*)d_in[4];
    const float* W_k  = (const float*)d_in[5];
    const float* b_k  = (const float*)d_in[6];
    const float* W_v  = (const float*)d_in[7];
    const float* b_v  = (const float*)d_in[8];
    const float* W_o  = (const float*)d_in[9];
    const float* b_o  = (const float*)d_in[10];
    float* out = (float*)d_out;

    const int n_pos = out_size / 3;          // 262144
    attn_fused_kernel<<<1024, 256>>>(z, W_in, b_in, W_q, b_q, W_k, b_k,
                                     W_v, b_v, W_o, b_o, out, n_pos);
}